// round 16
// baseline (speedup 1.0000x reference)
#include <cuda_runtime.h>
#include <cuda_fp16.h>
#include <math.h>
#include <stdint.h>

#define B_    8
#define C_    512
#define N_    4096
#define MTOT  32768
#define DH    64
#define GSLICE 4

// ---------------------------------------------------------------------------
// helpers (portable PTX only: cp.async, ldmatrix, mma.sync)
// ---------------------------------------------------------------------------
__device__ __forceinline__ uint32_t smem_u32(const void* p) {
    uint32_t a;
    asm("{ .reg .u64 t; cvta.to.shared.u64 t, %1; cvt.u32.u64 %0, t; }" : "=r"(a) : "l"(p));
    return a;
}
__device__ __forceinline__ void cp_async16(uint32_t dst, const void* src) {
    asm volatile("cp.async.cg.shared.global [%0], [%1], 16;" :: "r"(dst), "l"(src));
}
#define CP_COMMIT() asm volatile("cp.async.commit_group;" ::: "memory")
#define CP_WAIT(n)  asm volatile("cp.async.wait_group %0;" :: "n"(n) : "memory")

#define LDSM_X4(r, a)                                                          \
    asm volatile("ldmatrix.sync.aligned.m8n8.x4.shared.b16 {%0,%1,%2,%3},[%4];"\
        : "=r"((r)[0]), "=r"((r)[1]), "=r"((r)[2]), "=r"((r)[3]) : "r"(a))

#define LDSM_X4_T(r, a)                                                        \
    asm volatile("ldmatrix.sync.aligned.m8n8.x4.trans.shared.b16 {%0,%1,%2,%3},[%4];"\
        : "=r"((r)[0]), "=r"((r)[1]), "=r"((r)[2]), "=r"((r)[3]) : "r"(a))

__device__ __forceinline__ void mma16816(float* d, const uint32_t* a, const uint32_t* b) {
    asm volatile("mma.sync.aligned.m16n8k16.row.col.f32.f16.f16.f32 "
        "{%0,%1,%2,%3},{%4,%5,%6,%7},{%8,%9},{%0,%1,%2,%3};"
        : "+f"(d[0]), "+f"(d[1]), "+f"(d[2]), "+f"(d[3])
        : "r"(a[0]), "r"(a[1]), "r"(a[2]), "r"(a[3]), "r"(b[0]), "r"(b[1]));
}

// ---------------------------------------------------------------------------
// scratch
// ---------------------------------------------------------------------------
__device__ __half g_qkvh [MTOT * 1536];   // q|k|v
__device__ __half g_knvsh[MTOT * 1024];   // kn|vs
__device__ __half g_qnh  [MTOT * C_];
__device__ __half g_wh   [MTOT * C_];     // v * prior
__device__ __half g_oh   [MTOT * C_];
__device__ __half g_p2h  [MTOT * C_];
__device__ float  g_ab   [B_ * C_ * C_];
__device__ __half g_xh [MTOT * C_];
__device__ __half g_ih [MTOT * C_];
__device__ __half g_sh [MTOT * C_];
__device__ __half g_knTh[B_ * C_ * N_], g_knTl[B_ * C_ * N_];
__device__ __half g_qnTh[B_ * C_ * N_], g_qnTl[B_ * C_ * N_];
__device__ __half g_abh[B_ * C_ * C_],  g_abl[B_ * C_ * C_];
__device__ __half g_w3h[1536 * C_], g_w3l[1536 * C_];
__device__ __half g_w2h[1024 * C_], g_w2l[1024 * C_];
__device__ __half g_wqh[C_ * C_],   g_wql[C_ * C_];
__device__ __half g_wph[C_ * C_],   g_wpl[C_ * C_];
__device__ float g_Gp [GSLICE * 64 * 64 * 64];
__device__ float g_nkp[GSLICE * 64 * 64];
__device__ float g_nqp[GSLICE * 64 * 64];
__device__ __half g_attnh[64 * 64 * 64];
__device__ __half g_attnl[64 * 64 * 64];

// ---------------------------------------------------------------------------
// HMMA GEMM, PASSES = 1 (AhBh), 2 (+AhBl), 3 (+AlBh).
// CTA 128x128, BK=32, 8 warps, 3-stage cp.async, 80B-padded smem rows.
// ---------------------------------------------------------------------------
#define TILE_B   10240            // 128 rows * 80 B

template <int PASSES, int MINB>
__global__ __launch_bounds__(256, MINB) void gemm_h(
    const __half* __restrict__ Ah, const __half* __restrict__ Al,
    const __half* __restrict__ Bh, const __half* __restrict__ Bl,
    float* __restrict__ C, int K, int ldA, int ldB, int ldC,
    long sA, long sB, long sC,
    const float* __restrict__ bias,
    const __half* __restrict__ resH, int ldRes, long sRes,
    float alpha,
    __half* __restrict__ outH, int ldH, long sH,
    const __half* __restrict__ vmulH, int ldV, long sV)
{
    constexpr int NT = PASSES + 1;        // tiles per stage
    constexpr int STAGE_B = NT * TILE_B;
    extern __shared__ char smem[];
    const int m0 = blockIdx.y * 128, n0 = blockIdx.x * 128;
    Ah += blockIdx.z * sA;
    if (PASSES == 3) Al += blockIdx.z * sA;
    Bh += blockIdx.z * sB;
    if (PASSES >= 2) Bl += blockIdx.z * sB;
    if (C)     C     += blockIdx.z * sC;
    if (resH)  resH  += blockIdx.z * sRes;
    if (outH)  outH  += blockIdx.z * sH;
    if (vmulH) vmulH += blockIdx.z * sV;

    const int tid = threadIdx.x;
    const int wid = tid >> 5, lane = tid & 31;
    const int wm = (wid & 1) * 64;
    const int wn = (wid >> 1) * 32;
    const uint32_t sbase = smem_u32(smem);

    float acc[4][4][4];
#pragma unroll
    for (int i = 0; i < 4; i++)
#pragma unroll
        for (int j = 0; j < 4; j++)
#pragma unroll
            for (int p = 0; p < 4; p++) acc[i][j][p] = 0.f;

    const int KB = K >> 5;

#define STAGE_LOAD(kb, buf) do {                                               \
    int k0 = (kb) << 5;                                                        \
    uint32_t st = sbase + (buf) * STAGE_B;                                     \
    _Pragma("unroll")                                                          \
    for (int pos = 0; pos < 2; pos++) {                                        \
        int idx = tid + pos * 256;                                             \
        int r = idx >> 2, cc = idx & 3;                                        \
        uint32_t so = (uint32_t)(r * 80 + cc * 16);                            \
        long ga = (long)(m0 + r) * ldA + k0 + cc * 8;                          \
        long gb = (long)(n0 + r) * ldB + k0 + cc * 8;                          \
        cp_async16(st + so,          Ah + ga);                                 \
        cp_async16(st + TILE_B + so, Bh + gb);                                 \
        if (PASSES >= 2) cp_async16(st + 2 * TILE_B + so, Bl + gb);            \
        if (PASSES == 3) cp_async16(st + 3 * TILE_B + so, Al + ga);            \
    }                                                                          \
    CP_COMMIT();                                                               \
} while (0)

    STAGE_LOAD(0, 0);
    STAGE_LOAD(1, 1);

    const int lg = lane >> 3, lr = lane & 7;
    int cbuf = 0, lbuf = 2;

    for (int kb = 0; kb < KB; kb++) {
        if (kb + 1 < KB) CP_WAIT(1); else CP_WAIT(0);
        __syncthreads();
        if (kb + 2 < KB) STAGE_LOAD(kb + 2, lbuf);
        uint32_t st = sbase + cbuf * STAGE_B;

#pragma unroll
        for (int ks = 0; ks < 2; ks++) {
            const int cb = ks * 2;
            uint32_t ah[4][4], al[4][4], bh[4][2], bl[4][2];
#pragma unroll
            for (int mi = 0; mi < 4; mi++) {
                int row = wm + mi * 16 + lr + (lg & 1) * 8;
                int ch  = cb + (lg >> 1);
                uint32_t a = st + (uint32_t)(row * 80 + ch * 16);
                LDSM_X4(ah[mi], a);
                if (PASSES == 3) LDSM_X4(al[mi], a + 3 * TILE_B);
            }
#pragma unroll
            for (int np = 0; np < 2; np++) {
                int row = wn + np * 16 + lr + (lg >> 1) * 8;
                int ch  = cb + (lg & 1);
                uint32_t a = st + TILE_B + (uint32_t)(row * 80 + ch * 16);
                uint32_t t4[4];
                LDSM_X4(t4, a);
                bh[np * 2][0] = t4[0]; bh[np * 2][1] = t4[1];
                bh[np * 2 + 1][0] = t4[2]; bh[np * 2 + 1][1] = t4[3];
                if (PASSES >= 2) {
                    LDSM_X4(t4, a + TILE_B);
                    bl[np * 2][0] = t4[0]; bl[np * 2][1] = t4[1];
                    bl[np * 2 + 1][0] = t4[2]; bl[np * 2 + 1][1] = t4[3];
                }
            }
#pragma unroll
            for (int mi = 0; mi < 4; mi++)
#pragma unroll
                for (int nj = 0; nj < 4; nj++) {
                    mma16816(acc[mi][nj], ah[mi], bh[nj]);
                    if (PASSES >= 2) mma16816(acc[mi][nj], ah[mi], bl[nj]);
                    if (PASSES == 3) mma16816(acc[mi][nj], al[mi], bh[nj]);
                }
        }
        cbuf = (cbuf == 2) ? 0 : cbuf + 1;
        lbuf = (lbuf == 2) ? 0 : lbuf + 1;
    }

    const int er = lane >> 2, ec = (lane & 3) * 2;
#pragma unroll
    for (int mi = 0; mi < 4; mi++)
#pragma unroll
        for (int nj = 0; nj < 4; nj++) {
            int col = n0 + wn + nj * 8 + ec;
#pragma unroll
            for (int p = 0; p < 2; p++) {
                int row = m0 + wm + mi * 16 + er + p * 8;
                float2 v;
                v.x = acc[mi][nj][p * 2 + 0] * alpha;
                v.y = acc[mi][nj][p * 2 + 1] * alpha;
                if (bias) { v.x += bias[col]; v.y += bias[col + 1]; }
                if (resH) {
                    __half2 r2 = *(const __half2*)(resH + (long)row * ldRes + col);
                    v.x += __half2float(__low2half(r2));
                    v.y += __half2float(__high2half(r2));
                }
                if (vmulH) {
                    __half2 m2 = *(const __half2*)(vmulH + (long)row * ldV + col);
                    v.x *= __half2float(__low2half(m2));
                    v.y *= __half2float(__high2half(m2));
                }
                if (C) *(float2*)(C + (long)row * ldC + col) = v;
                if (outH)
                    *(__half2*)(outH + (long)row * ldH + col) =
                        __halves2half2(__float2half_rn(v.x), __float2half_rn(v.y));
            }
        }
}

// ---------------------------------------------------------------------------
// fused fp32 -> fp16 for x, illu, sem
// ---------------------------------------------------------------------------
__global__ void split_hi3(const float* __restrict__ a, const float* __restrict__ b,
                          const float* __restrict__ c,
                          __half* __restrict__ ha, __half* __restrict__ hb,
                          __half* __restrict__ hc, long n4)
{
    long i = ((long)blockIdx.x * blockDim.x + threadIdx.x);
    if (i >= n4) return;
    i *= 4;
    float4 va = *(const float4*)(a + i);
    float4 vb = *(const float4*)(b + i);
    float4 vc = *(const float4*)(c + i);
    *(__half2*)(ha + i)     = __halves2half2(__float2half_rn(va.x), __float2half_rn(va.y));
    *(__half2*)(ha + i + 2) = __halves2half2(__float2half_rn(va.z), __float2half_rn(va.w));
    *(__half2*)(hb + i)     = __halves2half2(__float2half_rn(vb.x), __float2half_rn(vb.y));
    *(__half2*)(hb + i + 2) = __halves2half2(__float2half_rn(vb.z), __float2half_rn(vb.w));
    *(__half2*)(hc + i)     = __halves2half2(__float2half_rn(vc.x), __float2half_rn(vc.y));
    *(__half2*)(hc + i + 2) = __halves2half2(__float2half_rn(vc.z), __float2half_rn(vc.w));
}

// ---------------------------------------------------------------------------
// transpose + split (weights): fp32 [R,C](ldIn) -> fp16 hi/lo [C,R](ldOut)
// ---------------------------------------------------------------------------
__global__ void transpose_split(const float* __restrict__ in, int ldIn, long sIn,
                                __half* __restrict__ oh, __half* __restrict__ ol,
                                int ldOut, long sOut)
{
    in += blockIdx.z * sIn; oh += blockIdx.z * sOut; ol += blockIdx.z * sOut;
    __shared__ float tile[32][33];
    int c0 = blockIdx.x * 32, r0 = blockIdx.y * 32;
    int tx = threadIdx.x, ty = threadIdx.y;
#pragma unroll
    for (int i = 0; i < 4; i++)
        tile[ty + 8 * i][tx] = in[(long)(r0 + ty + 8 * i) * ldIn + c0 + tx];
    __syncthreads();
#pragma unroll
    for (int i = 0; i < 4; i++) {
        float v = tile[tx][ty + 8 * i];
        __half hh = __float2half_rn(v);
        long o = (long)(c0 + ty + 8 * i) * ldOut + r0 + tx;
        oh[o] = hh;
        ol[o] = __float2half_rn(v - __half2float(hh));
    }
}

// ---------------------------------------------------------------------------
// FUSED: LayerNorm rows (512, fp16 in) + transpose + fp16 hi/lo split.
// ---------------------------------------------------------------------------
#define LDT 516
#define LNT_SMEM (32 * LDT * 4)   // 66048 B

__global__ __launch_bounds__(256) void ln_t_split(
    const __half* __restrict__ in, int ldIn, long sIn,
    const float* __restrict__ gg, const float* __restrict__ bb,
    __half* __restrict__ oh, __half* __restrict__ ol, long sOut)
{
    extern __shared__ float tile[];
    in += blockIdx.y * sIn; oh += blockIdx.y * sOut; ol += blockIdx.y * sOut;
    const int r0 = blockIdx.x * 32;
    const int t = threadIdx.x;

#pragma unroll
    for (int i = 0; i < 8; i++) {
        int lin = t + i * 256;
        int r = lin >> 6, c8 = (lin & 63) * 8;
        uint4 raw = *(const uint4*)(in + (long)(r0 + r) * ldIn + c8);
        const __half2* hp = (const __half2*)&raw;
        float* dst = &tile[r * LDT + c8];
#pragma unroll
        for (int j = 0; j < 4; j++) {
            dst[j * 2 + 0] = __half2float(__low2half(hp[j]));
            dst[j * 2 + 1] = __half2float(__high2half(hp[j]));
        }
    }
    __syncthreads();

    __shared__ float mu_s[32], inv_s[32];
    const int w = t >> 5, lane = t & 31;
#pragma unroll
    for (int rr = 0; rr < 4; rr++) {
        int r = w * 4 + rr;
        float s = 0.f, q = 0.f;
#pragma unroll
        for (int i = 0; i < 16; i++) {
            float v = tile[r * LDT + lane + i * 32];
            s += v; q += v * v;
        }
#pragma unroll
        for (int o = 16; o; o >>= 1) {
            s += __shfl_xor_sync(0xffffffffu, s, o);
            q += __shfl_xor_sync(0xffffffffu, q, o);
        }
        if (lane == 0) {
            float mu = s * (1.f / C_);
            mu_s[r]  = mu;
            inv_s[r] = rsqrtf(q * (1.f / C_) - mu * mu + 1e-5f);
        }
    }
    __syncthreads();

    const int r = t & 31, cg = t >> 5;
    const float mu = mu_s[r], inv = inv_s[r];
#pragma unroll 8
    for (int cc = 0; cc < 64; cc++) {
        int c = cc * 8 + cg;
        float v = (tile[r * LDT + c] - mu) * inv * gg[c] + bb[c];
        __half hh = __float2half_rn(v);
        long o = (long)c * N_ + r0 + r;
        oh[o] = hh;
        ol[o] = __float2half_rn(v - __half2float(hh));
    }
}

// ---------------------------------------------------------------------------
// SIF softmax rows -> fp16 hi/lo (row-major)
// ---------------------------------------------------------------------------
__global__ void softmax_ab(const float* __restrict__ Ab,
                           __half* __restrict__ oh, __half* __restrict__ ol)
{
    long bi = blockIdx.x;
    const float* row = Ab + bi * 512;
    int t = threadIdx.x;
    float4 v = *(const float4*)(row + t * 4);
    float m = fmaxf(fmaxf(v.x, v.y), fmaxf(v.z, v.w));
#pragma unroll
    for (int o = 16; o; o >>= 1) m = fmaxf(m, __shfl_xor_sync(0xffffffffu, m, o));
    __shared__ float rm[4], rs[4];
    if ((t & 31) == 0) rm[t >> 5] = m;
    __syncthreads();
    m = fmaxf(fmaxf(rm[0], rm[1]), fmaxf(rm[2], rm[3]));
    float4 e;
    e.x = expf(v.x - m); e.y = expf(v.y - m);
    e.z = expf(v.z - m); e.w = expf(v.w - m);
    float s = e.x + e.y + e.z + e.w;
#pragma unroll
    for (int o = 16; o; o >>= 1) s += __shfl_xor_sync(0xffffffffu, s, o);
    if ((t & 31) == 0) rs[t >> 5] = s;
    __syncthreads();
    s = rs[0] + rs[1] + rs[2] + rs[3];
    float inv = 1.f / s;
    e.x *= inv; e.y *= inv; e.z *= inv; e.w *= inv;
    long o = bi * 512 + t * 4;
    __half hx = __float2half_rn(e.x), hy = __float2half_rn(e.y);
    __half hz = __float2half_rn(e.z), hw = __float2half_rn(e.w);
    *(__half2*)(oh + o)     = __halves2half2(hx, hy);
    *(__half2*)(oh + o + 2) = __halves2half2(hz, hw);
    *(__half2*)(ol + o) = __halves2half2(
        __float2half_rn(e.x - __half2float(hx)),
        __float2half_rn(e.y - __half2float(hy)));
    *(__half2*)(ol + o + 2) = __halves2half2(
        __float2half_rn(e.z - __half2float(hz)),
        __float2half_rn(e.w - __half2float(hw)));
}

// ---------------------------------------------------------------------------
// HMMA msa_g: Gram partials G[d,e] = sum_n k[n,d] q[n,e] + norms.
// ---------------------------------------------------------------------------
#define GW 144

__global__ __launch_bounds__(256, 2) void msa_g_hmma()
{
    __shared__ char sm[2 * 64 * GW];            // k tile, q tile
    __shared__ float nk_s[4][64], nq_s[4][64];
    const int bh = blockIdx.x, sl = blockIdx.y;
    const int b = bh >> 3, h = bh & 7;
    const int NS = N_ / GSLICE;                 // 1024
    const int n0 = sl * NS;
    const uint32_t sb = smem_u32(sm);
    const int tid = threadIdx.x;
    const __half* qb = g_qkvh + (long)b * N_ * 1536 + h * DH;
    const __half* kb = qb + 512;

    const int wid = tid >> 5, lane = tid & 31;
    const int mi = (wid & 3) * 16;              // d tile base
    const int wn = (wid >> 2) * 32;             // e group base
    const int lg = lane >> 3, lr = lane & 7;

    float acc[4][4];
#pragma unroll
    for (int j = 0; j < 4; j++)
#pragma unroll
        for (int p = 0; p < 4; p++) acc[j][p] = 0.f;
    float ssk = 0.f, ssq = 0.f;
    const int ncol = tid & 63, ng = tid >> 6;

    for (int nb = 0; nb < NS; nb += 64) {
#pragma unroll
        for (int i = 0; i < 2; i++) {
            int idx = tid + i * 256;
            int r = idx >> 3, cc = idx & 7;
            long g = (long)(n0 + nb + r) * 1536 + cc * 8;
            cp_async16(sb + (uint32_t)(r * GW + cc * 16),           kb + g);
            cp_async16(sb + (uint32_t)(64 * GW + r * GW + cc * 16), qb + g);
        }
        CP_COMMIT();
        CP_WAIT(0);
        __syncthreads();

#pragma unroll
        for (int i = 0; i < 16; i++) {
            int r = ng * 16 + i;
            float kv = __half2float(*(const __half*)(sm + r * GW + ncol * 2));
            float qv = __half2float(*(const __half*)(sm + 64 * GW + r * GW + ncol * 2));
            ssk += kv * kv; ssq += qv * qv;
        }

#pragma unroll
        for (int ks = 0; ks < 4; ks++) {
            uint32_t aT[4];
            {
                uint32_t a = sb + (uint32_t)((ks * 16 + lr + (lg >> 1) * 8) * GW
                                             + (mi + (lg & 1) * 8) * 2);
                LDSM_X4_T(aT, a);
            }
#pragma unroll
            for (int np = 0; np < 2; np++) {
                uint32_t t4[4];
                {
                    uint32_t a = sb + (uint32_t)(64 * GW
                        + (ks * 16 + lr + (lg & 1) * 8) * GW
                        + (wn + np * 16 + (lg >> 1) * 8) * 2);
                    LDSM_X4_T(t4, a);
                }
                uint32_t b0[2] = { t4[0], t4[1] };
                uint32_t b1[2] = { t4[2], t4[3] };
                mma16816(acc[np * 2],     aT, b0);
                mma16816(acc[np * 2 + 1], aT, b1);
            }
        }
        __syncthreads();
    }

    const int er = lane >> 2, ec = (lane & 3) * 2;
    float* Gb = g_Gp + ((long)sl * 64 + bh) * 4096;
#pragma unroll
    for (int nj = 0; nj < 4; nj++) {
        int e = wn + nj * 8 + ec;
#pragma unroll
        for (int p = 0; p < 2; p++) {
            int d = mi + er + p * 8;
            *(float2*)(Gb + d * 64 + e) =
                make_float2(acc[nj][p * 2 + 0], acc[nj][p * 2 + 1]);
        }
    }
    nk_s[ng][ncol] = ssk;
    nq_s[ng][ncol] = ssq;
    __syncthreads();
    if (tid < 64) {
        float sk = nk_s[0][tid] + nk_s[1][tid] + nk_s[2][tid] + nk_s[3][tid];
        float sq = nq_s[0][tid] + nq_s[1][tid] + nq_s[2][tid] + nq_s[3][tid];
        g_nkp[((long)sl * 64 + bh) * 64 + tid] = sk;
        g_nqp[((long)sl * 64 + bh) * 64 + tid] = sq;
    }
}

// reduce partials + softmax -> attn fp16 hi/lo
__global__ void msa_soft(const float* __restrict__ rescale)
{
    int r = blockIdx.x;
    int bh = r >> 6, d = r & 63, h = bh & 7;
    int t = threadIdx.x;
    float gsum = 0.f, nks = 0.f, nqs = 0.f;
#pragma unroll
    for (int sl = 0; sl < GSLICE; sl++) {
        gsum += g_Gp[((long)sl * 64 + bh) * 4096 + d * 64 + t];
        nks  += g_nkp[((long)sl * 64 + bh) * 64 + d];
        nqs  += g_nqp[((long)sl * 64 + bh) * 64 + t];
    }
    float nk = fmaxf(sqrtf(nks), 1e-12f);
    float nq = fmaxf(sqrtf(nqs), 1e-12f);
    float val = gsum * (rescale[h] / (nk * nq));
    float m = val;
#pragma unroll
    for (int o = 16; o; o >>= 1) m = fmaxf(m, __shfl_xor_sync(0xffffffffu, m, o));
    __shared__ float rm[2], rs[2];
    if ((t & 31) == 0) rm[t >> 5] = m;
    __syncthreads();
    m = fmaxf(rm[0], rm[1]);
    float e = expf(val - m);
    float s = e;
#pragma unroll
    for (int o = 16; o; o >>= 1) s += __shfl_xor_sync(0xffffffffu, s, o);
    if ((t & 31) == 0) rs[t >> 5] = s;
    __syncthreads();
    s = rs[0] + rs[1];
    float v = e / s;
    __half hh = __float2half_rn(v);
    long o = (long)bh * 4096 + d * 64 + t;
    g_attnh[o] = hh;
    g_attnl[o] = __float2half_rn(v - __half2float(hh));
}

// ---------------------------------------------------------------------------
// HMMA msa_o: per (bh, m-tile) o[n, h*64+d] = sum_e w[n,e] attn[d,e]
// ---------------------------------------------------------------------------
#define MOW 144

__global__ __launch_bounds__(256, 2) void msa_o_hmma()
{
    __shared__ char sm[128 * MOW + 2 * 64 * MOW];
    const int mt = blockIdx.x, bh = blockIdx.y;
    const int b = bh >> 3, h = bh & 7;
    const uint32_t sb = smem_u32(sm);
    const int tid = threadIdx.x;
    const int n0 = mt * 128;

    const __half* wb = g_wh + (long)b * N_ * C_ + h * DH;
#pragma unroll
    for (int i = 0; i < 4; i++) {
        int idx = tid + i * 256;
        int r = idx >> 3, cc = idx & 7;
        *(uint4*)(sm + r * MOW + cc * 16) =
            *(const uint4*)(wb + (long)(n0 + r) * C_ + cc * 8);
    }
    const __half* ah_ = g_attnh + (long)bh * 4096;
    const __half* al_ = g_attnl + (long)bh * 4096;
#pragma unroll
    for (int i = 0; i < 2; i++) {
        int idx = tid + i * 256;
        int r = idx >> 3, cc = idx & 7;
        *(uint4*)(sm + 128 * MOW + r * MOW + cc * 16) =
            *(const uint4*)(ah_ + r * 64 + cc * 8);
        *(uint4*)(sm + 192 * MOW + r * MOW + cc * 16) =
            *(const uint4*)(al_ + r * 64 + cc * 8);
    }
    __syncthreads();

    const int wid = tid >> 5, lane = tid & 31;
    const int wm = wid * 16;
    const int lg = lane >> 3, lr = lane & 7;

    float acc[8][4];
#pragma unroll
    for (int j = 0; j < 8; j++)
#pragma unroll
        for (int p = 0; p < 4; p++) acc[j][p] = 0.f;

#pragma unroll
    for (int ks = 0; ks < 4; ks++) {
        const int cb = ks * 2;
        uint32_t a4[4], bhf[8][2], blf[8][2];
        {
            int row = wm + lr + (lg & 1) * 8;
            int ch  = cb + (lg >> 1);
            LDSM_X4(a4, sb + (uint32_t)(row * MOW + ch * 16));
        }
#pragma unroll
        for (int np = 0; np < 4; np++) {
            int row = np * 16 + lr + (lg >> 1) * 8;
            int ch  = cb + (lg & 1);
            uint32_t a = sb + (uint32_t)(128 * MOW + row * MOW + ch * 16);
            uint32_t t4[4];
            LDSM_X4(t4, a);
            bhf[np * 2][0] = t4[0]; bhf[np * 2][1] = t4[1];
            bhf[np * 2 + 1][0] = t4[2]; bhf[np * 2 + 1][1] = t4[3];
            LDSM_X4(t4, a + 64 * MOW);
            blf[np * 2][0] = t4[0]; blf[np * 2][1] = t4[1];
            blf[np * 2 + 1][0] = t4[2]; blf[np * 2 + 1][1] = t4[3];
        }
#pragma unroll
        for (int nj = 0; nj < 8; nj++) {
            mma16816(acc[nj], a4, bhf[nj]);
            mma16816(acc[nj], a4, blf[nj]);
        }
    }

    const int er = lane >> 2, ec = (lane & 3) * 2;
    const long obase = (long)b * N_ * C_ + h * DH;
#pragma unroll
    for (int nj = 0; nj < 8; nj++) {
        int d = nj * 8 + ec;
#pragma unroll
        for (int p = 0; p < 2; p++) {
            int row = n0 + wm + er + p * 8;
            *(__half2*)(g_oh + obase + (long)row * C_ + d) =
                __halves2half2(__float2half_rn(acc[nj][p * 2 + 0]),
                               __float2half_rn(acc[nj][p * 2 + 1]));
        }
    }
}

// ---------------------------------------------------------------------------
// FUSED depthwise conv pair: p2 = dw2 * gelu(dw1 * v), spatially tiled.
// FIX vs R15: mid (gelu output) positions OUTSIDE the image are forced to 0
// (reference zero-pads the gelu field for conv2).
// ---------------------------------------------------------------------------
#define DWI 12
#define DWP 10
#define DW_SMEM ((DWI * DWI + DWP * DWP) * 128 * 2)   // 62464 B

__device__ __forceinline__ float gelu_exact(float x)
{
    return 0.5f * x * (1.f + erff(x * 0.70710678118654752f));
}

__global__ __launch_bounds__(256) void dwconv_fused(
    const __half* __restrict__ in, int ldIn,
    const float* __restrict__ w1, const float* __restrict__ w2,
    __half* __restrict__ outp)
{
    extern __shared__ __half sdw[];
    __half* s_in = sdw;                    // [144][128]
    __half* s_p1 = sdw + DWI * DWI * 128;  // [100][128]
    const int tile = blockIdx.x, b = blockIdx.y, cgrp = blockIdx.z;
    const int ty = (tile >> 3) * 8, tx = (tile & 7) * 8;
    const int t = threadIdx.x;
    const int cq = t & 31;
    const int pg = t >> 5;
    const int chb = cgrp * 128;
    const int ch = chb + cq * 4;

    // load 12x12 input tile (zero-padded at image borders)
    for (int i = t; i < DWI * DWI * 16; i += 256) {
        int pix = i >> 4, ck = i & 15;
        int iy = pix / DWI, ix = pix - iy * DWI;
        int gy = ty - 2 + iy, gx = tx - 2 + ix;
        uint4 val = make_uint4(0, 0, 0, 0);
        if (gy >= 0 && gy < 64 && gx >= 0 && gx < 64)
            val = *(const uint4*)(in + ((long)(b << 12) + (gy << 6) + gx) * ldIn + chb + ck * 8);
        *(uint4*)(s_in + pix * 128 + ck * 8) = val;
    }

    float wr[3][3][4];
#pragma unroll
    for (int ky = 0; ky < 3; ky++)
#pragma unroll
        for (int kx = 0; kx < 3; kx++)
#pragma unroll
            for (int i = 0; i < 4; i++)
                wr[ky][kx][i] = w1[(long)(ch + i) * 9 + ky * 3 + kx];
    __syncthreads();

    // phase 1: conv1 + GELU -> fp16 mid (10x10); mid outside image := 0
    for (int p = pg; p < DWP * DWP; p += 8) {
        int py = p / DWP, px = p - py * DWP;
        int gy = ty - 1 + py, gx = tx - 1 + px;
        __half* op = s_p1 + p * 128 + cq * 4;
        if (gy < 0 || gy > 63 || gx < 0 || gx > 63) {
            *(__half2*)op       = __halves2half2(__float2half_rn(0.f), __float2half_rn(0.f));
            *(__half2*)(op + 2) = __halves2half2(__float2half_rn(0.f), __float2half_rn(0.f));
            continue;
        }
        float a0 = 0.f, a1 = 0.f, a2 = 0.f, a3 = 0.f;
#pragma unroll
        for (int ky = 0; ky < 3; ky++)
#pragma unroll
            for (int kx = 0; kx < 3; kx++) {
                const __half* bp = s_in + ((py + ky) * DWI + (px + kx)) * 128 + cq * 4;
                __half2 h0 = *(const __half2*)bp;
                __half2 h1 = *(const __half2*)(bp + 2);
                a0 += __half2float(__low2half(h0))  * wr[ky][kx][0];
                a1 += __half2float(__high2half(h0)) * wr[ky][kx][1];
                a2 += __half2float(__low2half(h1))  * wr[ky][kx][2];
                a3 += __half2float(__high2half(h1)) * wr[ky][kx][3];
            }
        *(__half2*)op       = __halves2half2(__float2half_rn(gelu_exact(a0)),
                                             __float2half_rn(gelu_exact(a1)));
        *(__half2*)(op + 2) = __halves2half2(__float2half_rn(gelu_exact(a2)),
                                             __float2half_rn(gelu_exact(a3)));
    }

    // load conv2 weights (regs only)
#pragma unroll
    for (int ky = 0; ky < 3; ky++)
#pragma unroll
        for (int kx = 0; kx < 3; kx++)
#pragma unroll
            for (int i = 0; i < 4; i++)
                wr[ky][kx][i] = w2[(long)(ch + i) * 9 + ky * 3 + kx];
    __syncthreads();

    // phase 2: conv2 -> p2 (8x8)
    for (int p = pg; p < 64; p += 8) {
        int oy = p >> 3, ox = p & 7;
        float a0 = 0.f, a1 = 0.f, a2 = 0.f, a3 = 0.f;
#pragma unroll
        for (int ky = 0; ky < 3; ky++)
#pragma unroll
            for (int kx = 0; kx < 3; kx++) {
                const __half* bp = s_p1 + ((oy + ky) * DWP + (ox + kx)) * 128 + cq * 4;
                __half2 h0 = *(const __half2*)bp;
                __half2 h1 = *(const __half2*)(bp + 2);
                a0 += __half2float(__low2half(h0))  * wr[ky][kx][0];
                a1 += __half2float(__high2half(h0)) * wr[ky][kx][1];
                a2 += __half2float(__low2half(h1))  * wr[ky][kx][2];
                a3 += __half2float(__high2half(h1)) * wr[ky][kx][3];
            }
        long off = ((long)(b << 12) + ((ty + oy) << 6) + tx + ox) * C_ + ch;
        *(__half2*)(outp + off)     = __halves2half2(__float2half_rn(a0), __float2half_rn(a1));
        *(__half2*)(outp + off + 2) = __halves2half2(__float2half_rn(a2), __float2half_rn(a3));
    }
}

// ---------------------------------------------------------------------------
// host
// ---------------------------------------------------------------------------
extern "C" void kernel_launch(void* const* d_in, const int* in_sizes, int n_in,
                              void* d_out, int out_size)
{
    const float* x       = (const float*)d_in[0];
    const float* illu    = (const float*)d_in[1];
    const float* sem     = (const float*)d_in[2];
    const float* Wk_sif  = (const float*)d_in[3];
    const float* Wq_sif  = (const float*)d_in[4];
    const float* Wv_sif  = (const float*)d_in[5];
    const float* ln_g    = (const float*)d_in[6];
    const float* ln_b    = (const float*)d_in[7];
    const float* Wq      = (const float*)d_in[8];
    const float* Wk      = (const float*)d_in[9];
    const float* Wv      = (const float*)d_in[10];
    const float* rescale = (const float*)d_in[11];
    const float* proj_w  = (const float*)d_in[12];
    const float* proj_b  = (const float*)d_in[13];
    const float* dw1     = (const float*)d_in[14];
    const float* dw2     = (const float*)d_in[15];
    float* out = (float*)d_out;

    static cudaStream_t s1 = nullptr, s2 = nullptr;
    static cudaEvent_t evA = nullptr, evP = nullptr, evM = nullptr;
    if (s1 == nullptr) {
        cudaStreamCreateWithFlags(&s1, cudaStreamNonBlocking);
        cudaStreamCreateWithFlags(&s2, cudaStreamNonBlocking);
        cudaEventCreateWithFlags(&evA, cudaEventDisableTiming);
        cudaEventCreateWithFlags(&evP, cudaEventDisableTiming);
        cudaEventCreateWithFlags(&evM, cudaEventDisableTiming);
    }

    cudaFuncSetAttribute((const void*)gemm_h<1, 2>, cudaFuncAttributeMaxDynamicSharedMemorySize, 3 * 2 * TILE_B);
    cudaFuncSetAttribute((const void*)gemm_h<2, 2>, cudaFuncAttributeMaxDynamicSharedMemorySize, 3 * 3 * TILE_B);
    cudaFuncSetAttribute((const void*)gemm_h<3, 1>, cudaFuncAttributeMaxDynamicSharedMemorySize, 3 * 4 * TILE_B);
    cudaFuncSetAttribute((const void*)ln_t_split, cudaFuncAttributeMaxDynamicSharedMemorySize, LNT_SMEM);
    cudaFuncSetAttribute((const void*)dwconv_fused, cudaFuncAttributeMaxDynamicSharedMemorySize, DW_SMEM);

#define SYM(p, s) do { void* _t; cudaGetSymbolAddress(&_t, s); p = (decltype(p))_t; } while (0)
    float *ab;
    __half *qkvh, *knvsh, *qnh, *wh, *oh, *p2h;
    __half *xh, *ih, *sh;
    __half *knTh, *knTl, *qnTh, *qnTl, *abh, *abl;
    __half *w3h, *w3l, *w2h, *w2l, *wqh, *wql, *wph, *wpl;
    SYM(ab, g_ab);
    SYM(qkvh, g_qkvh); SYM(knvsh, g_knvsh); SYM(qnh, g_qnh);
    SYM(wh, g_wh); SYM(oh, g_oh); SYM(p2h, g_p2h);
    SYM(xh, g_xh); SYM(ih, g_ih); SYM(sh, g_sh);
    SYM(knTh, g_knTh); SYM(knTl, g_knTl); SYM(qnTh, g_qnTh); SYM(qnTl, g_qnTl);
    SYM(abh, g_abh); SYM(abl, g_abl);
    SYM(w3h, g_w3h); SYM(w3l, g_w3l); SYM(w2h, g_w2h); SYM(w2l, g_w2l);
    SYM(wqh, g_wqh); SYM(wql, g_wql); SYM(wph, g_wph); SYM(wpl, g_wpl);

    dim3 tb(32, 8);
    dim3 tw(16, 16, 1);
    transpose_split<<<tw, tb>>>(Wq,     C_, 0, w3h,               w3l,               C_, 0);
    transpose_split<<<tw, tb>>>(Wk,     C_, 0, w3h + C_ * C_,     w3l + C_ * C_,     C_, 0);
    transpose_split<<<tw, tb>>>(Wv,     C_, 0, w3h + 2 * C_ * C_, w3l + 2 * C_ * C_, C_, 0);
    transpose_split<<<tw, tb>>>(Wk_sif, C_, 0, w2h,               w2l,               C_, 0);
    transpose_split<<<tw, tb>>>(Wv_sif, C_, 0, w2h + C_ * C_,     w2l + C_ * C_,     C_, 0);
    transpose_split<<<tw, tb>>>(Wq_sif, C_, 0, wqh,               wql,               C_, 0);
    transpose_split<<<tw, tb>>>(proj_w, C_, 0, wph,               wpl,               C_, 0);

    long n4 = (long)MTOT * C_ / 4;
    split_hi3<<<(unsigned)((n4 + 255) / 256), 256>>>(x, illu, sem, xh, ih, sh, n4);

    // GEMM1 (1-pass): qkv(fp16) = x @ [Wq|Wk|Wv]
    gemm_h<1, 2><<<dim3(12, 256, 1), 256, 3 * 2 * TILE_B>>>(xh, nullptr, w3h, nullptr,
        nullptr, C_, C_, C_, 0, 0, 0, 0, nullptr, nullptr, 0, 0, 1.f,
        qkvh, 1536, 0, nullptr, 0, 0);
    cudaEventRecord(evA, 0);

    // --- fork: fused positional branch on s1 (needs v from GEMM1) ---
    cudaStreamWaitEvent(s1, evA, 0);
    dwconv_fused<<<dim3(64, 8, 4), 256, DW_SMEM, s1>>>(qkvh + 1024, 1536, dw1, dw2, p2h);
    cudaEventRecord(evP, s1);

    // --- fork: MSA Gram branch on s2 (needs q,k from GEMM1) ---
    cudaStreamWaitEvent(s2, evA, 0);
    msa_g_hmma<<<dim3(64, GSLICE), 256, 0, s2>>>();
    msa_soft<<<64 * 64, 64, 0, s2>>>(rescale);
    cudaEventRecord(evM, s2);

    // --- SIF spine on default stream ---
    gemm_h<1, 2><<<dim3(8, 256, 1), 256, 3 * 2 * TILE_B>>>(ih, nullptr, w2h, nullptr,
        nullptr, C_, C_, C_, 0, 0, 0, 0, nullptr, nullptr, 0, 0, 1.f,
        knvsh, 1024, 0, nullptr, 0, 0);
    gemm_h<1, 2><<<dim3(4, 256, 1), 256, 3 * 2 * TILE_B>>>(sh, nullptr, wqh, nullptr,
        nullptr, C_, C_, C_, 0, 0, 0, 0, nullptr, nullptr, 0, 0, 1.f,
        qnh, 512, 0, nullptr, 0, 0);

    ln_t_split<<<dim3(128, 8), 256, LNT_SMEM>>>(knvsh, 1024, (long)N_ * 1024,
        ln_g, ln_b, knTh, knTl, (long)C_ * N_);
    ln_t_split<<<dim3(128, 8), 256, LNT_SMEM>>>(qnh, 512, (long)N_ * 512,
        ln_g, ln_b, qnTh, qnTl, (long)C_ * N_);

    // GEMM4 (3-pass): Ab[b] = (Qn^T Kn)/sqrt(C)
    gemm_h<3, 1><<<dim3(4, 4, 8), 256, 3 * 4 * TILE_B>>>(qnTh, qnTl, knTh, knTl,
        ab, N_, N_, N_, C_, (long)C_ * N_, (long)C_ * N_, (long)C_ * C_,
        nullptr, nullptr, 0, 0, 0.044194173824159216f, nullptr, 0, 0, nullptr, 0, 0);

    softmax_ab<<<B_ * C_, 128>>>(ab, abh, abl);

    // GEMM5 (1-pass): w(fp16) = (V@Ab^T + V) * v
    gemm_h<1, 2><<<dim3(4, 32, 8), 256, 3 * 2 * TILE_B>>>(knvsh + 512, nullptr, abh, nullptr,
        nullptr, C_, 1024, C_, 0, (long)N_ * 1024, (long)C_ * C_, 0,
        nullptr, knvsh + 512, 1024, (long)N_ * 1024, 1.f,
        wh, 512, (long)N_ * C_, qkvh + 1024, 1536, (long)N_ * 1536);

    // --- join: msa_o needs attn (s2) + w (default) ---
    cudaStreamWaitEvent(0, evM, 0);
    msa_o_hmma<<<dim3(32, 64), 256>>>();

    // --- join: GEMM6 needs p2 (s1) + o (default) ---
    cudaStreamWaitEvent(0, evP, 0);
    gemm_h<2, 2><<<dim3(4, 256, 1), 256, 3 * 3 * TILE_B>>>(oh, nullptr, wph, wpl,
        out, C_, C_, C_, C_, 0, 0, 0, proj_b, p2h, C_, 0, 1.f,
        nullptr, 0, 0, nullptr, 0, 0);
}